// round 1
// baseline (speedup 1.0000x reference)
#include <cuda_runtime.h>
#include <cstdint>
#include <math.h>

#define S_LEN 128
#define B_SZ  128
#define E_DIM 64
#define H_DIM 8
#define V_SZ  30000
#define T_OUT 12
#define NSAMP (S_LEN * B_SZ)
#define FULLM 0xffffffffu

// ---------------- device scratch (no allocations allowed) ----------------
__device__ float g_zx[NSAMP * 32];     // precomputed x-part of z, per (s*128+b, g*8+q)
__device__ float g_h[NSAMP * H_DIM];   // hidden states, row = b*128 + s == QFC sample id
__device__ int   g_is64;               // sentence dtype flag

// ---------------- fixed random-layer ops (computed host-side, passed by value) ----
struct GateOp { int kind; int a; int b; float c; float s; };  // kind: 0 rx,1 ry,2 rz,3 cnot
struct OpsArg { GateOp op[30]; };

// =================== kernel 0: detect sentence dtype ===================
__global__ void k_detect(const long long* __restrict__ s64) {
    if (threadIdx.x == 0 && blockIdx.x == 0) {
        int cnt = 0;
        for (int i = 0; i < 128; i++) {
            long long v = s64[i];
            if (v >= 0 && v < V_SZ) cnt++;
        }
        g_is64 = (cnt >= 64) ? 1 : 0;
    }
}

// =================== kernel 1: zx = emb[sentence] @ Win[:,:,:64]^T ===================
// one warp per flat sample n = s*128+b ; lane = g*8+q
__global__ void k_embed(const float* __restrict__ emb,
                        const float* __restrict__ Win,
                        const long long* __restrict__ sent) {
    int warp = (blockIdx.x * blockDim.x + threadIdx.x) >> 5;
    int lane = threadIdx.x & 31;
    if (warp >= NSAMP) return;
    long long tok;
    if (g_is64) tok = sent[warp];
    else        tok = (long long)(((const int*)sent)[warp]);
    const float4* er = reinterpret_cast<const float4*>(emb + (size_t)tok * E_DIM);
    const float4* wr = reinterpret_cast<const float4*>(Win + lane * 72);
    float a0 = 0.f, a1 = 0.f, a2 = 0.f, a3 = 0.f;
#pragma unroll
    for (int k = 0; k < 16; k++) {
        float4 e4 = er[k];
        float4 w4 = wr[k];
        a0 += e4.x * w4.x; a1 += e4.y * w4.y;
        a2 += e4.z * w4.z; a3 += e4.w * w4.w;
    }
    g_zx[warp * 32 + lane] = (a0 + a1) + (a2 + a3);
}

// =================== kernel 2: LSTM recurrence (1 warp per batch element) ===================
__device__ __forceinline__ float fsig(float x) { return 1.f / (1.f + __expf(-x)); }
__device__ __forceinline__ float ftanh(float x) {
    float ax = fabsf(x);
    float t = 1.f - 2.f / (__expf(2.f * ax) + 1.f);
    return copysignf(t, x);
}

__global__ void k_lstm(const float* __restrict__ Win,
                       const float* __restrict__ b_in,
                       const float* __restrict__ phi,
                       const float* __restrict__ Wout,
                       const float* __restrict__ b_out) {
    int b = blockIdx.x;
    int lane = threadIdx.x;      // lane = g*8 + q  (also reused as g*8 + h)
    float Wh[8], Wo[8];
#pragma unroll
    for (int j = 0; j < 8; j++) Wh[j] = Win[lane * 72 + 64 + j];
#pragma unroll
    for (int j = 0; j < 8; j++) Wo[j] = Wout[lane * 8 + j];
    float bphi = b_in[lane] + phi[lane];
    float bo = b_out[lane];
    float hv[8];
#pragma unroll
    for (int j = 0; j < 8; j++) hv[j] = 0.f;
    float cst = 0.f;
    int hh = lane & 7;
    int base = lane & 24;

    for (int s = 0; s < S_LEN; s++) {
        float z = g_zx[(s * B_SZ + b) * 32 + lane] + bphi;
#pragma unroll
        for (int j = 0; j < 8; j++) z += Wh[j] * hv[j];
        float p = __cosf(z);
        // inclusive cumprod over q within groups of 8 lanes
#pragma unroll
        for (int d = 1; d < 8; d <<= 1) {
            float t = __shfl_up_sync(FULLM, p, d, 8);
            if ((lane & 7) >= d) p *= t;
        }
        // pre[g,h] at lane g*8+h
        float acc = bo;
#pragma unroll
        for (int q = 0; q < 8; q++) acc += Wo[q] * __shfl_sync(FULLM, p, base + q);
        float pf = __shfl_sync(FULLM, acc, hh);
        float pi = __shfl_sync(FULLM, acc, 8 + hh);
        float pg = __shfl_sync(FULLM, acc, 16 + hh);
        float po = __shfl_sync(FULLM, acc, 24 + hh);
        float f = fsig(pf), ig = fsig(pi), gg = ftanh(pg), og = fsig(po);
        cst = f * cst + ig * gg;
        float hnew = og * ftanh(cst);
#pragma unroll
        for (int j = 0; j < 8; j++) hv[j] = __shfl_sync(FULLM, hnew, j);
        if (lane < 8) g_h[(b * S_LEN + s) * H_DIM + lane] = hnew;
    }
}

// =================== kernel 3: QFC statevector head ===================
// wire w (0..7) -> amp bit position p = 7-w. p>=3 : lane bit (p-3). p<3 : register bit.
// state: 8 complex amps/lane, amp index = (lane<<3)|j.

template<int P>
__device__ __forceinline__ void rx_local(float* re, float* im, float c, float s) {
#pragma unroll
    for (int e = 0; e < 8; e++) {
        if (e & (1 << P)) continue;
        int o = e | (1 << P);
        float a0r = re[e], a0i = im[e], a1r = re[o], a1i = im[o];
        re[e] = c * a0r + s * a1i; im[e] = c * a0i - s * a1r;
        re[o] = c * a1r + s * a0i; im[o] = c * a1i - s * a0r;
    }
}

template<int P>
__device__ __forceinline__ void ry_local(float* re, float* im, float c, float s) {
#pragma unroll
    for (int e = 0; e < 8; e++) {
        if (e & (1 << P)) continue;
        int o = e | (1 << P);
        float a0r = re[e], a0i = im[e], a1r = re[o], a1i = im[o];
        re[e] = c * a0r - s * a1r; im[e] = c * a0i - s * a1i;
        re[o] = s * a0r + c * a1r; im[o] = s * a0i + c * a1i;
    }
}

__device__ __forceinline__ void rx_lane(float* re, float* im, float c, float s, int lmask) {
#pragma unroll
    for (int j = 0; j < 8; j++) {
        float orr = __shfl_xor_sync(FULLM, re[j], lmask);
        float oii = __shfl_xor_sync(FULLM, im[j], lmask);
        re[j] = c * re[j] + s * oii;
        im[j] = c * im[j] - s * orr;
    }
}

__device__ __forceinline__ void ry_lane(float* re, float* im, float c, float s, int lmask, int bit) {
    float t = bit ? s : -s;
#pragma unroll
    for (int j = 0; j < 8; j++) {
        float orr = __shfl_xor_sync(FULLM, re[j], lmask);
        float oii = __shfl_xor_sync(FULLM, im[j], lmask);
        re[j] = c * re[j] + t * orr;
        im[j] = c * im[j] + t * oii;
    }
}

__device__ __forceinline__ void rz_any(float* re, float* im, float c, float s, int p, int lane) {
#pragma unroll
    for (int j = 0; j < 8; j++) {
        int idx = (lane << 3) | j;
        float t = ((idx >> p) & 1) ? -s : s;
        float r = re[j], i = im[j];
        re[j] = c * r + t * i;
        im[j] = c * i - t * r;
    }
}

// CNOT, target = register bit PT. ctrl: lane_mode ? lctrl : reg bit pc of amp
template<int PT>
__device__ __forceinline__ void cswap_local(float* re, float* im, bool lane_mode, bool lctrl, int pc) {
#pragma unroll
    for (int e = 0; e < 8; e++) {
        if (e & (1 << PT)) continue;
        int o = e | (1 << PT);
        bool sw = lane_mode ? lctrl : (((e >> pc) & 1) != 0);
        float tr = re[e], ti = im[e];
        re[e] = sw ? re[o] : tr;   im[e] = sw ? im[o] : ti;
        re[o] = sw ? tr : re[o];   im[o] = sw ? ti : im[o];
    }
}

// CNOT, target = lane bit (lmask). ctrl: lane_mode ? ctrl_sel : reg bit pc of j
__device__ __forceinline__ void cnot_tlane(float* re, float* im, int lmask,
                                           bool lane_mode, int ctrl_sel, int pc) {
#pragma unroll
    for (int j = 0; j < 8; j++) {
        float orr = __shfl_xor_sync(FULLM, re[j], lmask);
        float oii = __shfl_xor_sync(FULLM, im[j], lmask);
        bool sw = lane_mode ? (ctrl_sel != 0) : (((j >> pc) & 1) != 0);
        re[j] = sw ? orr : re[j];
        im[j] = sw ? oii : im[j];
    }
}

__global__ void k_qfc(const float* __restrict__ phiq,
                      const float* __restrict__ Whead,
                      const float* __restrict__ b_head,
                      float* __restrict__ out,
                      OpsArg K) {
    int warp = (blockIdx.x * blockDim.x + threadIdx.x) >> 5;
    int lane = threadIdx.x & 31;
    if (warp >= NSAMP) return;

    float re[8], im[8];
    // ---- initial product state from RY(theta_w)|0> ----
    {
        float cs[8], sn[8];
#pragma unroll
        for (int w = 0; w < 8; w++) {
            float th = 0.5f * g_h[warp * 8 + w];
            cs[w] = __cosf(th);
            sn[w] = __sinf(th);
        }
        float fr = 1.f;
#pragma unroll
        for (int w = 0; w < 5; w++) {
            int bit = (lane >> (4 - w)) & 1;
            fr *= bit ? sn[w] : cs[w];
        }
#pragma unroll
        for (int j = 0; j < 8; j++) {
            float g = fr;
            g *= ((j >> 2) & 1) ? sn[5] : cs[5];
            g *= ((j >> 1) & 1) ? sn[6] : cs[6];
            g *= (j & 1) ? sn[7] : cs[7];
            re[j] = g;
            im[j] = 0.f;
        }
    }

    // ---- 30 fixed random-layer ops ----
    for (int t = 0; t < 30; t++) {
        int kind = K.op[t].kind;
        float c = K.op[t].c, s = K.op[t].s;
        int pa = 7 - K.op[t].a;
        if (kind == 3) {
            int pc = pa, pt = 7 - K.op[t].b;
            if (pt >= 3) {
                int lmask = 1 << (pt - 3);
                if (pc >= 3) {
                    int ctrl = (lane >> (pc - 3)) & 1;
                    cnot_tlane(re, im, lmask, true, ctrl, 0);
                } else {
                    cnot_tlane(re, im, lmask, false, 0, pc);
                }
            } else {
                bool lane_mode = (pc >= 3);
                bool lctrl = lane_mode ? (((lane >> (pc - 3)) & 1) != 0) : false;
                if (pt == 0)      cswap_local<0>(re, im, lane_mode, lctrl, pc);
                else if (pt == 1) cswap_local<1>(re, im, lane_mode, lctrl, pc);
                else              cswap_local<2>(re, im, lane_mode, lctrl, pc);
            }
        } else if (kind == 2) {
            rz_any(re, im, c, s, pa, lane);
        } else if (kind == 0) {
            if (pa >= 3)      rx_lane(re, im, c, s, 1 << (pa - 3));
            else if (pa == 0) rx_local<0>(re, im, c, s);
            else if (pa == 1) rx_local<1>(re, im, c, s);
            else              rx_local<2>(re, im, c, s);
        } else { // ry
            if (pa >= 3)      ry_lane(re, im, c, s, 1 << (pa - 3), (lane >> (pa - 3)) & 1);
            else if (pa == 0) ry_local<0>(re, im, c, s);
            else if (pa == 1) ry_local<1>(re, im, c, s);
            else              ry_local<2>(re, im, c, s);
        }
    }

    // ---- final fixed RX(phiq[w]) ----
#pragma unroll
    for (int w = 0; w < 5; w++) {
        float th = 0.5f * phiq[w];
        rx_lane(re, im, __cosf(th), __sinf(th), 1 << (4 - w));
    }
    { float th = 0.5f * phiq[5]; rx_local<2>(re, im, __cosf(th), __sinf(th)); }
    { float th = 0.5f * phiq[6]; rx_local<1>(re, im, __cosf(th), __sinf(th)); }
    { float th = 0.5f * phiq[7]; rx_local<0>(re, im, __cosf(th), __sinf(th)); }

    // ---- measure <Z_w> ----
    float zp[8];
    float tot = 0.f, z5 = 0.f, z6 = 0.f, z7 = 0.f;
#pragma unroll
    for (int j = 0; j < 8; j++) {
        float pj = re[j] * re[j] + im[j] * im[j];
        tot += pj;
        z5 += ((j >> 2) & 1) ? -pj : pj;
        z6 += ((j >> 1) & 1) ? -pj : pj;
        z7 += (j & 1) ? -pj : pj;
    }
#pragma unroll
    for (int w = 0; w < 5; w++) zp[w] = ((lane >> (4 - w)) & 1) ? -tot : tot;
    zp[5] = z5; zp[6] = z6; zp[7] = z7;
#pragma unroll
    for (int off = 16; off >= 1; off >>= 1) {
#pragma unroll
        for (int w = 0; w < 8; w++) zp[w] += __shfl_xor_sync(FULLM, zp[w], off);
    }

    // ---- head + log_softmax over T=12 (lanes 0..11) ----
    float logit = __int_as_float(0xff800000);  // -inf
    if (lane < T_OUT) {
        float a = b_head[lane];
#pragma unroll
        for (int h = 0; h < 8; h++) a += zp[h] * Whead[lane * 8 + h];
        logit = a;
    }
    float m = logit;
#pragma unroll
    for (int off = 16; off >= 1; off >>= 1) m = fmaxf(m, __shfl_xor_sync(FULLM, m, off));
    float e = (lane < T_OUT) ? __expf(logit - m) : 0.f;
#pragma unroll
    for (int off = 16; off >= 1; off >>= 1) e += __shfl_xor_sync(FULLM, e, off);
    if (lane < T_OUT) out[warp * T_OUT + lane] = logit - m - __logf(e);
}

// =================== host: numpy legacy RandomState(1234) replica ===================
static uint32_t s_mt[624];
static int s_mti;

static void mt_seed(uint32_t seed) {
    s_mt[0] = seed;
    for (int i = 1; i < 624; i++)
        s_mt[i] = 1812433253u * (s_mt[i - 1] ^ (s_mt[i - 1] >> 30)) + (uint32_t)i;
    s_mti = 624;
}

static uint32_t mt_next(void) {
    if (s_mti >= 624) {
        for (int i = 0; i < 624; i++) {
            uint32_t y = (s_mt[i] & 0x80000000u) | (s_mt[(i + 1) % 624] & 0x7fffffffu);
            s_mt[i] = s_mt[(i + 397) % 624] ^ (y >> 1) ^ ((y & 1u) ? 0x9908b0dfu : 0u);
        }
        s_mti = 0;
    }
    uint32_t y = s_mt[s_mti++];
    y ^= y >> 11;
    y ^= (y << 7) & 0x9d2c5680u;
    y ^= (y << 15) & 0xefc60000u;
    y ^= y >> 18;
    return y;
}

// legacy randint [0,n): masked rejection on 32-bit draws (rng fits in 32 bits)
static uint32_t np_ri(uint32_t n) {
    uint32_t rng = n - 1;
    uint32_t mask = rng;
    mask |= mask >> 1; mask |= mask >> 2; mask |= mask >> 4;
    mask |= mask >> 8; mask |= mask >> 16;
    uint32_t v;
    do { v = mt_next() & mask; } while (v > rng);
    return v;
}

// legacy random_sample (53-bit)
static double np_rs(void) {
    uint32_t a = mt_next() >> 5, b = mt_next() >> 6;
    return (a * 67108864.0 + b) * (1.0 / 9007199254740992.0);
}

static void build_ops(OpsArg* A) {
    const double TWO_PI = 6.283185307179586476925286766559;
    mt_seed(1234u);
    for (int t = 0; t < 30; t++) {
        uint32_t kind = np_ri(4);
        if (kind == 3) {  // n_wires >= 2 always
            int c = (int)np_ri(8);
            int tt = (int)np_ri(7);
            if (tt >= c) tt += 1;
            A->op[t].kind = 3; A->op[t].a = c; A->op[t].b = tt;
            A->op[t].c = 0.f;  A->op[t].s = 0.f;
        } else {
            int w = (int)np_ri(8);
            double ang = TWO_PI * np_rs();           // uniform(0, 2pi)
            float thf = (float)ang;                   // jnp.float32 cast
            float hf = thf * 0.5f;                    // th / 2 in fp32
            A->op[t].kind = (int)kind;  // 0 rx, 1 ry, 2 rz
            A->op[t].a = w; A->op[t].b = -1;
            A->op[t].c = (float)cos((double)hf);
            A->op[t].s = (float)sin((double)hf);
        }
    }
}

// =================== launcher ===================
extern "C" void kernel_launch(void* const* d_in, const int* in_sizes, int n_in,
                              void* d_out, int out_size) {
    const float* emb     = (const float*)d_in[0];
    const float* Win     = (const float*)d_in[1];
    const float* b_in    = (const float*)d_in[2];
    const float* phi     = (const float*)d_in[3];
    const float* Wout    = (const float*)d_in[4];
    const float* b_out   = (const float*)d_in[5];
    const float* phiq    = (const float*)d_in[6];
    const float* Whead   = (const float*)d_in[7];
    const float* b_head  = (const float*)d_in[8];
    const long long* sent = (const long long*)d_in[9];
    float* out = (float*)d_out;

    OpsArg K;
    build_ops(&K);

    k_detect<<<1, 32>>>(sent);
    k_embed<<<NSAMP / 8, 256>>>(emb, Win, sent);
    k_lstm<<<B_SZ, 32>>>(Win, b_in, phi, Wout, b_out);
    k_qfc<<<NSAMP / 8, 256>>>(phiq, Whead, b_head, out, K);
}

// round 2
// speedup vs baseline: 2.1318x; 2.1318x over previous
#include <cuda_runtime.h>
#include <cstdint>
#include <math.h>

#define S_LEN 128
#define B_SZ  128
#define E_DIM 64
#define H_DIM 8
#define V_SZ  30000
#define T_OUT 12
#define NSAMP (S_LEN * B_SZ)
#define FULLM 0xffffffffu

// ---------------- device scratch ----------------
__device__ float g_zx[NSAMP * 32];     // x-part of z per (s*128+b, g*8+q)
__device__ float g_h[NSAMP * H_DIM];   // hidden states, row = b*128 + s

// ======================================================================
// Compile-time numpy legacy RandomState(1234) replica -> fixed gate list
// ======================================================================
struct CtOps { int k[30]; int a[30]; int b[30]; double th[30]; };

__host__ __device__ constexpr void ct_twist(uint32_t* mt) {
    for (int i = 0; i < 624; i++) {
        uint32_t y = (mt[i] & 0x80000000u) | (mt[(i + 1) % 624] & 0x7fffffffu);
        mt[i] = mt[(i + 397) % 624] ^ (y >> 1) ^ ((y & 1u) ? 0x9908b0dfu : 0u);
    }
}
__host__ __device__ constexpr uint32_t ct_next(uint32_t* mt, int& mti) {
    if (mti >= 624) { ct_twist(mt); mti = 0; }
    uint32_t y = mt[mti++];
    y ^= y >> 11;
    y ^= (y << 7) & 0x9d2c5680u;
    y ^= (y << 15) & 0xefc60000u;
    y ^= y >> 18;
    return y;
}
__host__ __device__ constexpr uint32_t ct_ri(uint32_t* mt, int& mti, uint32_t n) {
    uint32_t rng = n - 1u, mask = rng;
    mask |= mask >> 1; mask |= mask >> 2; mask |= mask >> 4;
    mask |= mask >> 8; mask |= mask >> 16;
    uint32_t v = ct_next(mt, mti) & mask;
    while (v > rng) v = ct_next(mt, mti) & mask;
    return v;
}
__host__ __device__ constexpr double ct_rs(uint32_t* mt, int& mti) {
    uint32_t a = ct_next(mt, mti) >> 5, b = ct_next(mt, mti) >> 6;
    return (a * 67108864.0 + b) * (1.0 / 9007199254740992.0);
}
__host__ __device__ constexpr CtOps ct_build() {
    uint32_t mt[624] = {};
    mt[0] = 1234u;
    for (int i = 1; i < 624; i++)
        mt[i] = 1812433253u * (mt[i - 1] ^ (mt[i - 1] >> 30)) + (uint32_t)i;
    int mti = 624;
    CtOps R{};
    const double TWO_PI = 6.283185307179586476925286766559;
    for (int t = 0; t < 30; t++) {
        uint32_t kind = ct_ri(mt, mti, 4u);
        if (kind == 3u) {
            int c = (int)ct_ri(mt, mti, 8u);
            int tt = (int)ct_ri(mt, mti, 7u);
            if (tt >= c) tt += 1;
            R.k[t] = 3; R.a[t] = c; R.b[t] = tt; R.th[t] = 0.0;
        } else {
            int w = (int)ct_ri(mt, mti, 8u);
            R.k[t] = (int)kind; R.a[t] = w; R.b[t] = 0;
            R.th[t] = TWO_PI * ct_rs(mt, mti);
        }
    }
    return R;
}
static constexpr CtOps OPS = ct_build();

// constexpr trig (double, x in [0, pi]) — Taylor, converges to full precision
__host__ __device__ constexpr double ct_cos(double x) {
    double t = 1.0, sum = 1.0;
    for (int k = 1; k <= 20; k++) { t *= -x * x / ((2.0 * k - 1.0) * (2.0 * k)); sum += t; }
    return sum;
}
__host__ __device__ constexpr double ct_sin(double x) {
    double t = x, sum = x;
    for (int k = 1; k <= 20; k++) { t *= -x * x / ((2.0 * k) * (2.0 * k + 1.0)); sum += t; }
    return sum;
}

template<int T> struct OpK {
    static constexpr int   kind = OPS.k[T];
    static constexpr int   pa   = 7 - OPS.a[T];       // bit pos of wire a
    static constexpr int   pb   = 7 - OPS.b[T];       // bit pos of wire b (cnot target)
    static constexpr float thf  = (float)OPS.th[T];   // match ref: f32 cast of angle
    static constexpr float hf   = thf * 0.5f;
    static constexpr float c    = (float)ct_cos((double)hf);
    static constexpr float s    = (float)ct_sin((double)hf);
};

// ======================================================================
// k_embed: zx = emb[sentence] @ Win[:,:,:64]^T   (1 warp / sample)
// ======================================================================
__global__ void __launch_bounds__(256) k_embed(const float* __restrict__ emb,
                                               const float* __restrict__ Win,
                                               const long long* __restrict__ sent) {
    int warp = (blockIdx.x * blockDim.x + threadIdx.x) >> 5;
    int lane = threadIdx.x & 31;
    // inline dtype vote: int64 tokens are all in [0, V); int32-as-int64 qwords almost never
    int cnt = 0;
#pragma unroll
    for (int i = 0; i < 8; i++) {
        long long v = sent[i];
        cnt += (v >= 0 && v < V_SZ);
    }
    long long tok;
    if (cnt >= 5) tok = sent[warp];
    else          tok = (long long)(((const int*)sent)[warp]);
    const float4* er = reinterpret_cast<const float4*>(emb + (size_t)tok * E_DIM);
    const float4* wr = reinterpret_cast<const float4*>(Win + lane * 72);
    float a0 = 0.f, a1 = 0.f, a2 = 0.f, a3 = 0.f;
#pragma unroll
    for (int k = 0; k < 16; k++) {
        float4 e4 = er[k];
        float4 w4 = wr[k];
        a0 += e4.x * w4.x; a1 += e4.y * w4.y;
        a2 += e4.z * w4.z; a3 += e4.w * w4.w;
    }
    g_zx[warp * 32 + lane] = (a0 + a1) + (a2 + a3);
}

// ======================================================================
// k_lstm: recurrence, 1 warp per batch element, Horner-fused QGate
// ======================================================================
__device__ __forceinline__ float tanhfast(float x) {
    float y;
    asm("tanh.approx.f32 %0, %1;" : "=f"(y) : "f"(x));
    return y;
}

__global__ void __launch_bounds__(32) k_lstm(const float* __restrict__ Win,
                                             const float* __restrict__ b_in,
                                             const float* __restrict__ phi,
                                             const float* __restrict__ Wout,
                                             const float* __restrict__ b_out) {
    int b = blockIdx.x;
    int lane = threadIdx.x;                 // lane = g*8 + q  (also g*8 + h)
    float Wh[8], Wo[8];
#pragma unroll
    for (int j = 0; j < 8; j++) Wh[j] = Win[lane * 72 + 64 + j];
#pragma unroll
    for (int j = 0; j < 8; j++) Wo[j] = Wout[lane * 8 + j];
    float bphi = b_in[lane] + phi[lane];
    float bo = b_out[lane];

    float hn = 0.f;        // h for unit (lane&7), replicated across the 4 groups
    float cst = 0.f;       // c-state for unit (lane&7), replicated
    int hh = lane & 7;
    int base = lane & 24;
    bool isg = (base == 16);   // group 2 -> tanh, others sigmoid

    float zc = g_zx[(0 * B_SZ + b) * 32 + lane];
    float zn = g_zx[(1 * B_SZ + b) * 32 + lane];

    for (int s = 0; s < S_LEN; s++) {
        // prefetch s+2 (index clamped; value unused past end)
        int sp = (s + 2 < S_LEN) ? (s + 2) : (S_LEN - 1);
        float zn2 = g_zx[(sp * B_SZ + b) * 32 + lane];

        float z = zc + bphi;
#pragma unroll
        for (int j = 0; j < 8; j++) z = fmaf(Wh[j], __shfl_sync(FULLM, hn, j), z);
        float myc = __cosf(z);
        float cj[8];
#pragma unroll
        for (int j = 0; j < 8; j++) cj[j] = __shfl_sync(FULLM, myc, base + j);
        // Horner: pre = bo + c0*(Wo0 + c1*(Wo1 + ... + c7*Wo7))
        float t = Wo[7];
#pragma unroll
        for (int q = 6; q >= 0; q--) t = fmaf(cj[q + 1], t, Wo[q]);
        float pre = fmaf(cj[0], t, bo);
        // activation (branch-free): tanh for group 2, sigmoid otherwise
        float arg = isg ? pre : 0.5f * pre;
        float ta = tanhfast(arg);
        float a = isg ? ta : fmaf(0.5f, ta, 0.5f);
        // gather gates for this lane's unit
        float vf = __shfl_sync(FULLM, a, hh);
        float vi = __shfl_sync(FULLM, a, 8 + hh);
        float vg = __shfl_sync(FULLM, a, 16 + hh);
        float vo = __shfl_sync(FULLM, a, 24 + hh);
        cst = fmaf(vf, cst, vi * vg);
        hn = vo * tanhfast(cst);
        if (lane < 8) g_h[(b * S_LEN + s) * H_DIM + lane] = hn;
        zc = zn; zn = zn2;
    }
}

// ======================================================================
// k_qfc: 8-wire statevector, 1 warp/sample, fully specialized gate list
// wire w -> amp bit p = 7-w.  p>=3: lane bit (p-3).  p<3: register bit.
// amp index = (lane<<3) | j,  8 complex amps per lane in registers.
// ======================================================================
template<int P>
__device__ __forceinline__ void rx_loc(float re[8], float im[8], float c, float s) {
#pragma unroll
    for (int e = 0; e < 8; e++) {
        if (e & (1 << P)) continue;
        int o = e | (1 << P);
        float a0r = re[e], a0i = im[e], a1r = re[o], a1i = im[o];
        re[e] = c * a0r + s * a1i; im[e] = c * a0i - s * a1r;
        re[o] = c * a1r + s * a0i; im[o] = c * a1i - s * a0r;
    }
}
template<int P>
__device__ __forceinline__ void ry_loc(float re[8], float im[8], float c, float s) {
#pragma unroll
    for (int e = 0; e < 8; e++) {
        if (e & (1 << P)) continue;
        int o = e | (1 << P);
        float a0r = re[e], a0i = im[e], a1r = re[o], a1i = im[o];
        re[e] = c * a0r - s * a1r; im[e] = c * a0i - s * a1i;
        re[o] = s * a0r + c * a1r; im[o] = s * a0i + c * a1i;
    }
}
__device__ __forceinline__ void rx_lane(float re[8], float im[8], float c, float s, int m) {
#pragma unroll
    for (int j = 0; j < 8; j++) {
        float orr = __shfl_xor_sync(FULLM, re[j], m);
        float oii = __shfl_xor_sync(FULLM, im[j], m);
        re[j] = c * re[j] + s * oii;
        im[j] = c * im[j] - s * orr;
    }
}
__device__ __forceinline__ void ry_lane(float re[8], float im[8], float c, float s, int m, int bit) {
    float t = bit ? s : -s;
#pragma unroll
    for (int j = 0; j < 8; j++) {
        float orr = __shfl_xor_sync(FULLM, re[j], m);
        float oii = __shfl_xor_sync(FULLM, im[j], m);
        re[j] = c * re[j] + t * orr;
        im[j] = c * im[j] + t * oii;
    }
}

template<int T>
__device__ __forceinline__ void apply_one(float re[8], float im[8], int lane) {
    constexpr int kind = OpK<T>::kind;
    constexpr float c = OpK<T>::c;
    constexpr float s = OpK<T>::s;
    if constexpr (kind == 3) {
        constexpr int pc = OpK<T>::pa;
        constexpr int pt = OpK<T>::pb;
        if constexpr (pt >= 3) {
            constexpr int m = 1 << (pt - 3);
            if constexpr (pc >= 3) {
                int ctrl = (lane >> (pc - 3)) & 1;
#pragma unroll
                for (int j = 0; j < 8; j++) {
                    float orr = __shfl_xor_sync(FULLM, re[j], m);
                    float oii = __shfl_xor_sync(FULLM, im[j], m);
                    re[j] = ctrl ? orr : re[j];
                    im[j] = ctrl ? oii : im[j];
                }
            } else {
#pragma unroll
                for (int j = 0; j < 8; j++) {
                    if ((j >> pc) & 1) {   // compile-time after unroll
                        re[j] = __shfl_xor_sync(FULLM, re[j], m);
                        im[j] = __shfl_xor_sync(FULLM, im[j], m);
                    }
                }
            }
        } else {   // target is register bit -> pure permutation
            constexpr int tm = 1 << pt;
            if constexpr (pc >= 3) {
                if ((lane >> (pc - 3)) & 1) {
#pragma unroll
                    for (int e = 0; e < 8; e++) {
                        if (e & tm) continue;
                        int o = e | tm;
                        float tr = re[e]; re[e] = re[o]; re[o] = tr;
                        float ti = im[e]; im[e] = im[o]; im[o] = ti;
                    }
                }
            } else {
#pragma unroll
                for (int e = 0; e < 8; e++) {
                    if ((e & tm) || !((e >> pc) & 1)) continue;  // compile-time
                    int o = e | tm;
                    float tr = re[e]; re[e] = re[o]; re[o] = tr;
                    float ti = im[e]; im[e] = im[o]; im[o] = ti;
                }
            }
        }
    } else if constexpr (kind == 2) {      // rz
        constexpr int p = OpK<T>::pa;
        if constexpr (p >= 3) {
            int bit = (lane >> (p - 3)) & 1;
            float t = bit ? -s : s;
            float tn = -t;
#pragma unroll
            for (int j = 0; j < 8; j++) {
                float r = re[j], i = im[j];
                re[j] = fmaf(t, i, c * r);
                im[j] = fmaf(tn, r, c * i);
            }
        } else {
#pragma unroll
            for (int j = 0; j < 8; j++) {
                constexpr float dummy = 0.f; (void)dummy;
                float sg = ((j >> p) & 1) ? -s : s;   // constant after unroll
                float r = re[j], i = im[j];
                re[j] = fmaf(sg, i, c * r);
                im[j] = fmaf(-sg, r, c * i);
            }
        }
    } else if constexpr (kind == 0) {      // rx
        constexpr int p = OpK<T>::pa;
        if constexpr (p >= 3)      rx_lane(re, im, c, s, 1 << (p - 3));
        else if constexpr (p == 0) rx_loc<0>(re, im, c, s);
        else if constexpr (p == 1) rx_loc<1>(re, im, c, s);
        else                       rx_loc<2>(re, im, c, s);
    } else {                                // ry
        constexpr int p = OpK<T>::pa;
        if constexpr (p >= 3)      ry_lane(re, im, c, s, 1 << (p - 3), (lane >> (p - 3)) & 1);
        else if constexpr (p == 0) ry_loc<0>(re, im, c, s);
        else if constexpr (p == 1) ry_loc<1>(re, im, c, s);
        else                       ry_loc<2>(re, im, c, s);
    }
}

template<int T>
__device__ __forceinline__ void apply_seq(float re[8], float im[8], int lane) {
    if constexpr (T < 30) {
        apply_one<T>(re, im, lane);
        apply_seq<T + 1>(re, im, lane);
    }
}

__global__ void __launch_bounds__(256) k_qfc(const float* __restrict__ phiq,
                                             const float* __restrict__ Whead,
                                             const float* __restrict__ b_head,
                                             float* __restrict__ out) {
    int warp = (blockIdx.x * blockDim.x + threadIdx.x) >> 5;
    int lane = threadIdx.x & 31;

    float re[8], im[8];
    // ---- initial product state from RY(h_w)|0> ----
    {
        float cs[8], sn[8];
#pragma unroll
        for (int w = 0; w < 8; w++) {
            float th = 0.5f * g_h[warp * 8 + w];
            cs[w] = __cosf(th);
            sn[w] = __sinf(th);
        }
        float fr = 1.f;
#pragma unroll
        for (int w = 0; w < 5; w++) {
            int bit = (lane >> (4 - w)) & 1;
            fr *= bit ? sn[w] : cs[w];
        }
#pragma unroll
        for (int j = 0; j < 8; j++) {
            float g = fr;
            g *= ((j >> 2) & 1) ? sn[5] : cs[5];
            g *= ((j >> 1) & 1) ? sn[6] : cs[6];
            g *= (j & 1) ? sn[7] : cs[7];
            re[j] = g;
            im[j] = 0.f;
        }
    }

    // ---- 30 fixed gates, fully specialized at compile time ----
    apply_seq<0>(re, im, lane);

    // ---- final RX(phiq[w]) (runtime angles) ----
#pragma unroll
    for (int w = 0; w < 5; w++) {
        float th = 0.5f * phiq[w];
        rx_lane(re, im, __cosf(th), __sinf(th), 1 << (4 - w));
    }
    { float th = 0.5f * phiq[5]; rx_loc<2>(re, im, __cosf(th), __sinf(th)); }
    { float th = 0.5f * phiq[6]; rx_loc<1>(re, im, __cosf(th), __sinf(th)); }
    { float th = 0.5f * phiq[7]; rx_loc<0>(re, im, __cosf(th), __sinf(th)); }

    // ---- measure <Z_w> ----
    float zp[8];
    float tot = 0.f, z5 = 0.f, z6 = 0.f, z7 = 0.f;
#pragma unroll
    for (int j = 0; j < 8; j++) {
        float pj = re[j] * re[j] + im[j] * im[j];
        tot += pj;
        z5 += ((j >> 2) & 1) ? -pj : pj;
        z6 += ((j >> 1) & 1) ? -pj : pj;
        z7 += (j & 1) ? -pj : pj;
    }
#pragma unroll
    for (int w = 0; w < 5; w++) zp[w] = ((lane >> (4 - w)) & 1) ? -tot : tot;
    zp[5] = z5; zp[6] = z6; zp[7] = z7;
#pragma unroll
    for (int off = 16; off >= 1; off >>= 1) {
#pragma unroll
        for (int w = 0; w < 8; w++) zp[w] += __shfl_xor_sync(FULLM, zp[w], off);
    }

    // ---- head + log_softmax over T=12 (lanes 0..11) ----
    float logit = __int_as_float(0xff800000);
    if (lane < T_OUT) {
        float a = b_head[lane];
#pragma unroll
        for (int h = 0; h < 8; h++) a += zp[h] * Whead[lane * 8 + h];
        logit = a;
    }
    float m = logit;
#pragma unroll
    for (int off = 16; off >= 1; off >>= 1) m = fmaxf(m, __shfl_xor_sync(FULLM, m, off));
    float e = (lane < T_OUT) ? __expf(logit - m) : 0.f;
#pragma unroll
    for (int off = 16; off >= 1; off >>= 1) e += __shfl_xor_sync(FULLM, e, off);
    if (lane < T_OUT) out[warp * T_OUT + lane] = logit - m - __logf(e);
}

// ======================================================================
extern "C" void kernel_launch(void* const* d_in, const int* in_sizes, int n_in,
                              void* d_out, int out_size) {
    const float* emb     = (const float*)d_in[0];
    const float* Win     = (const float*)d_in[1];
    const float* b_in    = (const float*)d_in[2];
    const float* phi     = (const float*)d_in[3];
    const float* Wout    = (const float*)d_in[4];
    const float* b_out   = (const float*)d_in[5];
    const float* phiq    = (const float*)d_in[6];
    const float* Whead   = (const float*)d_in[7];
    const float* b_head  = (const float*)d_in[8];
    const long long* sent = (const long long*)d_in[9];
    float* out = (float*)d_out;

    k_embed<<<NSAMP / 8, 256>>>(emb, Win, sent);
    k_lstm<<<B_SZ, 32>>>(Win, b_in, phi, Wout, b_out);
    k_qfc<<<NSAMP / 8, 256>>>(phiq, Whead, b_head, out);
}

// round 3
// speedup vs baseline: 2.3518x; 1.1032x over previous
#include <cuda_runtime.h>
#include <cstdint>
#include <math.h>

#define S_LEN 128
#define B_SZ  128
#define E_DIM 64
#define H_DIM 8
#define V_SZ  30000
#define T_OUT 12
#define NSAMP (S_LEN * B_SZ)
#define FULLM 0xffffffffu

// ---------------- device scratch ----------------
__device__ float g_zx[NSAMP * 32];     // x-part of z per (s*128+b, g*8+q)
__device__ float g_h[NSAMP * H_DIM];   // hidden states, row = b*128 + s

// ======================================================================
// Compile-time numpy legacy RandomState(1234) replica -> fixed gate list
// ======================================================================
struct CtOps { int k[30]; int a[30]; int b[30]; double th[30]; };

__host__ __device__ constexpr void ct_twist(uint32_t* mt) {
    for (int i = 0; i < 624; i++) {
        uint32_t y = (mt[i] & 0x80000000u) | (mt[(i + 1) % 624] & 0x7fffffffu);
        mt[i] = mt[(i + 397) % 624] ^ (y >> 1) ^ ((y & 1u) ? 0x9908b0dfu : 0u);
    }
}
__host__ __device__ constexpr uint32_t ct_next(uint32_t* mt, int& mti) {
    if (mti >= 624) { ct_twist(mt); mti = 0; }
    uint32_t y = mt[mti++];
    y ^= y >> 11;
    y ^= (y << 7) & 0x9d2c5680u;
    y ^= (y << 15) & 0xefc60000u;
    y ^= y >> 18;
    return y;
}
__host__ __device__ constexpr uint32_t ct_ri(uint32_t* mt, int& mti, uint32_t n) {
    uint32_t rng = n - 1u, mask = rng;
    mask |= mask >> 1; mask |= mask >> 2; mask |= mask >> 4;
    mask |= mask >> 8; mask |= mask >> 16;
    uint32_t v = ct_next(mt, mti) & mask;
    while (v > rng) v = ct_next(mt, mti) & mask;
    return v;
}
__host__ __device__ constexpr double ct_rs(uint32_t* mt, int& mti) {
    uint32_t a = ct_next(mt, mti) >> 5, b = ct_next(mt, mti) >> 6;
    return (a * 67108864.0 + b) * (1.0 / 9007199254740992.0);
}
__host__ __device__ constexpr CtOps ct_build() {
    uint32_t mt[624] = {};
    mt[0] = 1234u;
    for (int i = 1; i < 624; i++)
        mt[i] = 1812433253u * (mt[i - 1] ^ (mt[i - 1] >> 30)) + (uint32_t)i;
    int mti = 624;
    CtOps R{};
    const double TWO_PI = 6.283185307179586476925286766559;
    for (int t = 0; t < 30; t++) {
        uint32_t kind = ct_ri(mt, mti, 4u);
        if (kind == 3u) {
            int c = (int)ct_ri(mt, mti, 8u);
            int tt = (int)ct_ri(mt, mti, 7u);
            if (tt >= c) tt += 1;
            R.k[t] = 3; R.a[t] = c; R.b[t] = tt; R.th[t] = 0.0;
        } else {
            int w = (int)ct_ri(mt, mti, 8u);
            R.k[t] = (int)kind; R.a[t] = w; R.b[t] = 0;
            R.th[t] = TWO_PI * ct_rs(mt, mti);
        }
    }
    return R;
}
static constexpr CtOps OPS = ct_build();

// constexpr trig (double) — Taylor, converges to full precision on [0, 2pi]
__host__ __device__ constexpr double ct_cos(double x) {
    double t = 1.0, sum = 1.0;
    for (int k = 1; k <= 25; k++) { t *= -x * x / ((2.0 * k - 1.0) * (2.0 * k)); sum += t; }
    return sum;
}
__host__ __device__ constexpr double ct_sin(double x) {
    double t = x, sum = x;
    for (int k = 1; k <= 25; k++) { t *= -x * x / ((2.0 * k) * (2.0 * k + 1.0)); sum += t; }
    return sum;
}

template<int T> struct OpK {
    static constexpr int   kind = OPS.k[T];
    static constexpr int   pa   = 7 - OPS.a[T];       // bit pos of wire a
    static constexpr int   pb   = 7 - OPS.b[T];       // bit pos of wire b (cnot target)
    static constexpr float thf  = (float)OPS.th[T];   // match ref: f32 cast of angle
    static constexpr float hf   = thf * 0.5f;
    static constexpr float c    = (float)ct_cos((double)hf);
    static constexpr float s    = (float)ct_sin((double)hf);
};

// ======================================================================
// k_embed v2: zx = emb[sentence] @ Win[:,:,:64]^T
// 1 warp / 8 samples; Win register-resident per lane via padded smem stage
// ======================================================================
#define SPW 8   // samples per warp

__global__ void __launch_bounds__(256) k_embed(const float* __restrict__ emb,
                                               const float* __restrict__ Win,
                                               const long long* __restrict__ sent) {
    __shared__ float sW[32 * 76];   // stride 76 floats = 19 float4 (gcd(19,8)=1 -> conflict-free)
    int tid = threadIdx.x;
    for (int i = tid; i < 32 * 72; i += 256) {
        int r = i / 72, cix = i - r * 72;
        sW[r * 76 + cix] = Win[i];
    }
    __syncthreads();

    int lane = tid & 31;
    int wid = blockIdx.x * (256 / 32) + (tid >> 5);   // 0 .. 2047

    // each lane's 64 weights (row o = lane of Win[:,:,:64], row-major stride 72)
    float W[64];
    {
        const float4* wr = reinterpret_cast<const float4*>(&sW[lane * 76]);
#pragma unroll
        for (int k = 0; k < 16; k++) {
            float4 v = wr[k];
            W[4 * k] = v.x; W[4 * k + 1] = v.y; W[4 * k + 2] = v.z; W[4 * k + 3] = v.w;
        }
    }

    // dtype vote: int64 tokens all land in [0,V); int32-as-int64 qwords almost never
    int cnt = 0;
#pragma unroll
    for (int i = 0; i < 8; i++) {
        long long v = sent[i];
        cnt += (v >= 0 && v < V_SZ);
    }
    bool is64 = (cnt >= 5);

    int base = wid * SPW;
    long long tok[SPW];
#pragma unroll
    for (int i = 0; i < SPW; i++)
        tok[i] = is64 ? sent[base + i] : (long long)(((const int*)sent)[base + i]);

#pragma unroll
    for (int i = 0; i < SPW; i++) {
        const float* er = emb + (size_t)tok[i] * E_DIM;
        float elo = er[lane];
        float ehi = er[32 + lane];
        float a0 = 0.f, a1 = 0.f, a2 = 0.f, a3 = 0.f;
#pragma unroll
        for (int k = 0; k < 32; k += 4) {
            a0 = fmaf(W[k],     __shfl_sync(FULLM, elo, k),     a0);
            a1 = fmaf(W[k + 1], __shfl_sync(FULLM, elo, k + 1), a1);
            a2 = fmaf(W[k + 2], __shfl_sync(FULLM, elo, k + 2), a2);
            a3 = fmaf(W[k + 3], __shfl_sync(FULLM, elo, k + 3), a3);
        }
#pragma unroll
        for (int k = 0; k < 32; k += 4) {
            a0 = fmaf(W[32 + k],     __shfl_sync(FULLM, ehi, k),     a0);
            a1 = fmaf(W[32 + k + 1], __shfl_sync(FULLM, ehi, k + 1), a1);
            a2 = fmaf(W[32 + k + 2], __shfl_sync(FULLM, ehi, k + 2), a2);
            a3 = fmaf(W[32 + k + 3], __shfl_sync(FULLM, ehi, k + 3), a3);
        }
        g_zx[(base + i) * 32 + lane] = (a0 + a1) + (a2 + a3);
    }
}

// ======================================================================
// k_lstm: recurrence, 1 warp per batch element, Horner-fused QGate
// ======================================================================
__device__ __forceinline__ float tanhfast(float x) {
    float y;
    asm("tanh.approx.f32 %0, %1;" : "=f"(y) : "f"(x));
    return y;
}

__global__ void __launch_bounds__(32) k_lstm(const float* __restrict__ Win,
                                             const float* __restrict__ b_in,
                                             const float* __restrict__ phi,
                                             const float* __restrict__ Wout,
                                             const float* __restrict__ b_out) {
    int b = blockIdx.x;
    int lane = threadIdx.x;                 // lane = g*8 + q  (also g*8 + h)
    float Wh[8], Wo[8];
#pragma unroll
    for (int j = 0; j < 8; j++) Wh[j] = Win[lane * 72 + 64 + j];
#pragma unroll
    for (int j = 0; j < 8; j++) Wo[j] = Wout[lane * 8 + j];
    float bphi = b_in[lane] + phi[lane];
    float bo = b_out[lane];

    float hn = 0.f;        // h for unit (lane&7), replicated across the 4 groups
    float cst = 0.f;       // c-state for unit (lane&7), replicated
    int hh = lane & 7;
    int base = lane & 24;
    bool isg = (base == 16);   // group 2 -> tanh, others sigmoid

    const float* zp = &g_zx[b * 32 + lane];
    float zc = zp[0];
    float zn = zp[B_SZ * 32];
    zp += 2 * B_SZ * 32;
    float* hp = &g_h[b * S_LEN * H_DIM + lane];

    for (int s = 0; s < S_LEN; s++) {
        float zn2 = (s + 2 < S_LEN) ? *zp : 0.f;
        zp += B_SZ * 32;

        // z = zc + bphi + Wh . h  (two independent FMA chains, depth 5)
        float za = zc + bphi, zb = 0.f;
#pragma unroll
        for (int j = 0; j < 4; j++) {
            za = fmaf(Wh[j],     __shfl_sync(FULLM, hn, j),     za);
            zb = fmaf(Wh[j + 4], __shfl_sync(FULLM, hn, j + 4), zb);
        }
        float myc = __cosf(za + zb);
        float cj[8];
#pragma unroll
        for (int j = 0; j < 8; j++) cj[j] = __shfl_sync(FULLM, myc, base + j);
        // Horner: pre = bo + c0*(Wo0 + c1*(Wo1 + ... + c7*Wo7))
        float t = Wo[7];
#pragma unroll
        for (int q = 6; q >= 0; q--) t = fmaf(cj[q + 1], t, Wo[q]);
        float pre = fmaf(cj[0], t, bo);
        // activation (branch-free): tanh for group 2, sigmoid otherwise
        float arg = isg ? pre : 0.5f * pre;
        float ta = tanhfast(arg);
        float a = isg ? ta : fmaf(0.5f, ta, 0.5f);
        // gather gates for this lane's unit
        float vf = __shfl_sync(FULLM, a, hh);
        float vi = __shfl_sync(FULLM, a, 8 + hh);
        float vg = __shfl_sync(FULLM, a, 16 + hh);
        float vo = __shfl_sync(FULLM, a, 24 + hh);
        cst = fmaf(vf, cst, vi * vg);
        hn = vo * tanhfast(cst);
        if (lane < 8) hp[s * H_DIM] = hn;
        zc = zn; zn = zn2;
    }
}

// ======================================================================
// k_qfc: 8-wire statevector, 1 warp/sample, fully specialized gate list
// wire w -> amp bit p = 7-w.  p>=3: lane bit (p-3).  p<3: register bit.
// amp index = (lane<<3) | j,  8 complex amps per lane in registers.
// ======================================================================
template<int P>
__device__ __forceinline__ void rx_loc(float re[8], float im[8], float c, float s) {
#pragma unroll
    for (int e = 0; e < 8; e++) {
        if (e & (1 << P)) continue;
        int o = e | (1 << P);
        float a0r = re[e], a0i = im[e], a1r = re[o], a1i = im[o];
        re[e] = c * a0r + s * a1i; im[e] = c * a0i - s * a1r;
        re[o] = c * a1r + s * a0i; im[o] = c * a1i - s * a0r;
    }
}
template<int P>
__device__ __forceinline__ void ry_loc(float re[8], float im[8], float c, float s) {
#pragma unroll
    for (int e = 0; e < 8; e++) {
        if (e & (1 << P)) continue;
        int o = e | (1 << P);
        float a0r = re[e], a0i = im[e], a1r = re[o], a1i = im[o];
        re[e] = c * a0r - s * a1r; im[e] = c * a0i - s * a1i;
        re[o] = s * a0r + c * a1r; im[o] = s * a0i + c * a1i;
    }
}
__device__ __forceinline__ void rx_lane(float re[8], float im[8], float c, float s, int m) {
#pragma unroll
    for (int j = 0; j < 8; j++) {
        float orr = __shfl_xor_sync(FULLM, re[j], m);
        float oii = __shfl_xor_sync(FULLM, im[j], m);
        re[j] = c * re[j] + s * oii;
        im[j] = c * im[j] - s * orr;
    }
}
__device__ __forceinline__ void ry_lane(float re[8], float im[8], float c, float s, int m, int bit) {
    float t = bit ? s : -s;
#pragma unroll
    for (int j = 0; j < 8; j++) {
        float orr = __shfl_xor_sync(FULLM, re[j], m);
        float oii = __shfl_xor_sync(FULLM, im[j], m);
        re[j] = c * re[j] + t * orr;
        im[j] = c * im[j] + t * oii;
    }
}

template<int T>
__device__ __forceinline__ void apply_one(float re[8], float im[8], int lane) {
    constexpr int kind = OpK<T>::kind;
    constexpr float c = OpK<T>::c;
    constexpr float s = OpK<T>::s;
    if constexpr (kind == 3) {
        constexpr int pc = OpK<T>::pa;
        constexpr int pt = OpK<T>::pb;
        if constexpr (pt >= 3) {
            constexpr int m = 1 << (pt - 3);
            if constexpr (pc >= 3) {
                int ctrl = (lane >> (pc - 3)) & 1;
#pragma unroll
                for (int j = 0; j < 8; j++) {
                    float orr = __shfl_xor_sync(FULLM, re[j], m);
                    float oii = __shfl_xor_sync(FULLM, im[j], m);
                    re[j] = ctrl ? orr : re[j];
                    im[j] = ctrl ? oii : im[j];
                }
            } else {
#pragma unroll
                for (int j = 0; j < 8; j++) {
                    if ((j >> pc) & 1) {   // compile-time after unroll
                        re[j] = __shfl_xor_sync(FULLM, re[j], m);
                        im[j] = __shfl_xor_sync(FULLM, im[j], m);
                    }
                }
            }
        } else {   // target is register bit -> pure permutation
            constexpr int tm = 1 << pt;
            if constexpr (pc >= 3) {
                if ((lane >> (pc - 3)) & 1) {
#pragma unroll
                    for (int e = 0; e < 8; e++) {
                        if (e & tm) continue;
                        int o = e | tm;
                        float tr = re[e]; re[e] = re[o]; re[o] = tr;
                        float ti = im[e]; im[e] = im[o]; im[o] = ti;
                    }
                }
            } else {
#pragma unroll
                for (int e = 0; e < 8; e++) {
                    if ((e & tm) || !((e >> pc) & 1)) continue;  // compile-time
                    int o = e | tm;
                    float tr = re[e]; re[e] = re[o]; re[o] = tr;
                    float ti = im[e]; im[e] = im[o]; im[o] = ti;
                }
            }
        }
    } else if constexpr (kind == 2) {      // rz
        constexpr int p = OpK<T>::pa;
        if constexpr (p >= 3) {
            int bit = (lane >> (p - 3)) & 1;
            float t = bit ? -s : s;
            float tn = -t;
#pragma unroll
            for (int j = 0; j < 8; j++) {
                float r = re[j], i = im[j];
                re[j] = fmaf(t, i, c * r);
                im[j] = fmaf(tn, r, c * i);
            }
        } else {
#pragma unroll
            for (int j = 0; j < 8; j++) {
                float sg = ((j >> p) & 1) ? -s : s;   // constant after unroll
                float r = re[j], i = im[j];
                re[j] = fmaf(sg, i, c * r);
                im[j] = fmaf(-sg, r, c * i);
            }
        }
    } else if constexpr (kind == 0) {      // rx
        constexpr int p = OpK<T>::pa;
        if constexpr (p >= 3)      rx_lane(re, im, c, s, 1 << (p - 3));
        else if constexpr (p == 0) rx_loc<0>(re, im, c, s);
        else if constexpr (p == 1) rx_loc<1>(re, im, c, s);
        else                       rx_loc<2>(re, im, c, s);
    } else {                                // ry
        constexpr int p = OpK<T>::pa;
        if constexpr (p >= 3)      ry_lane(re, im, c, s, 1 << (p - 3), (lane >> (p - 3)) & 1);
        else if constexpr (p == 0) ry_loc<0>(re, im, c, s);
        else if constexpr (p == 1) ry_loc<1>(re, im, c, s);
        else                       ry_loc<2>(re, im, c, s);
    }
}

template<int T>
__device__ __forceinline__ void apply_seq(float re[8], float im[8], int lane) {
    if constexpr (T < 30) {
        apply_one<T>(re, im, lane);
        apply_seq<T + 1>(re, im, lane);
    }
}

__global__ void __launch_bounds__(256) k_qfc(const float* __restrict__ phiq,
                                             const float* __restrict__ Whead,
                                             const float* __restrict__ b_head,
                                             float* __restrict__ out) {
    int warp = (blockIdx.x * blockDim.x + threadIdx.x) >> 5;
    int lane = threadIdx.x & 31;

    float re[8], im[8];
    // ---- initial product state from RY(h_w)|0> ----
    {
        float cs[8], sn[8];
#pragma unroll
        for (int w = 0; w < 8; w++) {
            float th = 0.5f * g_h[warp * 8 + w];
            cs[w] = __cosf(th);
            sn[w] = __sinf(th);
        }
        float fr = 1.f;
#pragma unroll
        for (int w = 0; w < 5; w++) {
            int bit = (lane >> (4 - w)) & 1;
            fr *= bit ? sn[w] : cs[w];
        }
#pragma unroll
        for (int j = 0; j < 8; j++) {
            float g = fr;
            g *= ((j >> 2) & 1) ? sn[5] : cs[5];
            g *= ((j >> 1) & 1) ? sn[6] : cs[6];
            g *= (j & 1) ? sn[7] : cs[7];
            re[j] = g;
            im[j] = 0.f;
        }
    }

    // ---- 30 fixed gates, fully specialized at compile time ----
    apply_seq<0>(re, im, lane);

    // ---- final RX(phiq[w]) (runtime angles) ----
#pragma unroll
    for (int w = 0; w < 5; w++) {
        float th = 0.5f * phiq[w];
        rx_lane(re, im, __cosf(th), __sinf(th), 1 << (4 - w));
    }
    { float th = 0.5f * phiq[5]; rx_loc<2>(re, im, __cosf(th), __sinf(th)); }
    { float th = 0.5f * phiq[6]; rx_loc<1>(re, im, __cosf(th), __sinf(th)); }
    { float th = 0.5f * phiq[7]; rx_loc<0>(re, im, __cosf(th), __sinf(th)); }

    // ---- measure <Z_w> ----
    float zp[8];
    float tot = 0.f, z5 = 0.f, z6 = 0.f, z7 = 0.f;
#pragma unroll
    for (int j = 0; j < 8; j++) {
        float pj = re[j] * re[j] + im[j] * im[j];
        tot += pj;
        z5 += ((j >> 2) & 1) ? -pj : pj;
        z6 += ((j >> 1) & 1) ? -pj : pj;
        z7 += (j & 1) ? -pj : pj;
    }
#pragma unroll
    for (int w = 0; w < 5; w++) zp[w] = ((lane >> (4 - w)) & 1) ? -tot : tot;
    zp[5] = z5; zp[6] = z6; zp[7] = z7;
#pragma unroll
    for (int off = 16; off >= 1; off >>= 1) {
#pragma unroll
        for (int w = 0; w < 8; w++) zp[w] += __shfl_xor_sync(FULLM, zp[w], off);
    }

    // ---- head + log_softmax over T=12 (lanes 0..11) ----
    float logit = __int_as_float(0xff800000);
    if (lane < T_OUT) {
        float a = b_head[lane];
#pragma unroll
        for (int h = 0; h < 8; h++) a += zp[h] * Whead[lane * 8 + h];
        logit = a;
    }
    float m = logit;
#pragma unroll
    for (int off = 16; off >= 1; off >>= 1) m = fmaxf(m, __shfl_xor_sync(FULLM, m, off));
    float e = (lane < T_OUT) ? __expf(logit - m) : 0.f;
#pragma unroll
    for (int off = 16; off >= 1; off >>= 1) e += __shfl_xor_sync(FULLM, e, off);
    if (lane < T_OUT) out[warp * T_OUT + lane] = logit - m - __logf(e);
}

// ======================================================================
extern "C" void kernel_launch(void* const* d_in, const int* in_sizes, int n_in,
                              void* d_out, int out_size) {
    const float* emb     = (const float*)d_in[0];
    const float* Win     = (const float*)d_in[1];
    const float* b_in    = (const float*)d_in[2];
    const float* phi     = (const float*)d_in[3];
    const float* Wout    = (const float*)d_in[4];
    const float* b_out   = (const float*)d_in[5];
    const float* phiq    = (const float*)d_in[6];
    const float* Whead   = (const float*)d_in[7];
    const float* b_head  = (const float*)d_in[8];
    const long long* sent = (const long long*)d_in[9];
    float* out = (float*)d_out;

    k_embed<<<NSAMP / SPW / 8, 256>>>(emb, Win, sent);
    k_lstm<<<B_SZ, 32>>>(Win, b_in, phi, Wout, b_out);
    k_qfc<<<NSAMP / 8, 256>>>(phiq, Whead, b_head, out);
}